// round 15
// baseline (speedup 1.0000x reference)
#include <cuda_runtime.h>
#include <cuda_bf16.h>
#include <cstdint>

#define D 64
#define MAXN 50176

// Scratch (static device globals — allocation-free). Referenced ONLY in
// device code (host-side symbol is an ATS-readable shadow — Round-2 bug).
__device__ float g_agg[MAXN * D];    // sum over dst of (h1[src] + e1)
__device__ float g_deg[MAXN];
__device__ float g_h1[MAXN * D];     // X @ Wn2n_u
__device__ float g_hu2[MAXN * D];    // X @ (W_n2e_u @ W_e2e_bot)
__device__ float g_hv2[MAXN * D];    // [S,X] @ (W_n2e_v @ W_e2e_bot)
__device__ float g_Wcu[D * D];
__device__ float g_Wcv[2 * D * D];
// tf32 B fragments, 2 sets: [0:4096) We2e_top, [4096:8192) We2n
// layout per set: [kstep 8][ntile 8][lane 32][2]
__device__ float g_Wmma[2 * 8 * 8 * 32 * 2];

// ---------------------------------------------------------------------------
__global__ void k_zero(int N) {
    int i = blockIdx.x * blockDim.x + threadIdx.x;
    int nv = N * D / 4;
    if (i < nv)
        reinterpret_cast<float4*>(g_agg)[i] = make_float4(0.f, 0.f, 0.f, 0.f);
    if (i < N) g_deg[i] = 0.0f;
}

// ---------------------------------------------------------------------------
// K0b: composite weights Wcu, Wcv + tf32 fragments of We2e_top and We2n
// ---------------------------------------------------------------------------
__global__ void k_wprep(const float* __restrict__ Wn2e_u,
                        const float* __restrict__ Wn2e_v,
                        const float* __restrict__ We2e,
                        const float* __restrict__ We2n) {
    int idx = blockIdx.x * blockDim.x + threadIdx.x;
    if (idx < D * D) {
        int r = idx >> 6, j = idx & 63;
        float s = 0.0f;
        #pragma unroll 8
        for (int t = 0; t < D; t++)
            s += __ldg(Wn2e_u + r * D + t) * __ldg(We2e + (D + t) * D + j);
        g_Wcu[idx] = s;
    } else if (idx < 3 * D * D) {
        int i2 = idx - D * D;
        int r = i2 >> 6, j = i2 & 63;
        float s = 0.0f;
        #pragma unroll 8
        for (int t = 0; t < D; t++)
            s += __ldg(Wn2e_v + r * D + t) * __ldg(We2e + (D + t) * D + j);
        g_Wcv[i2] = s;
    } else if (idx < 3 * D * D + 2 * 2048) {
        int i = idx - 3 * D * D;               // 0..4095
        int set = i >> 11;                     // 0: We2e_top, 1: We2n
        int j = i & 2047;
        int lane = j & 31, nt = (j >> 5) & 7, ks = j >> 8;
        int gid = lane >> 2, tig = lane & 3;
        const float* W = set ? We2n : We2e;    // We2e rows 0..63 = top
        float w0 = W[(ks * 8 + tig) * D + nt * 8 + gid];
        float w1 = W[(ks * 8 + tig + 4) * D + nt * 8 + gid];
        uint32_t t0, t1;
        asm("cvt.rna.tf32.f32 %0, %1;" : "=r"(t0) : "f"(w0));
        asm("cvt.rna.tf32.f32 %0, %1;" : "=r"(t1) : "f"(w1));
        g_Wmma[i * 2 + 0] = __uint_as_float(t0);
        g_Wmma[i * 2 + 1] = __uint_as_float(t1);
    }
}

// ---------------------------------------------------------------------------
// Tile loader: 64 rows x 64 feats transposed (node kernels)
// ---------------------------------------------------------------------------
__device__ __forceinline__ void load_tile_T(float (*sT)[65],
                                            const float* __restrict__ p,
                                            int base, int nRows, int tid) {
    for (int i = tid; i < 64 * 16; i += 256) {
        int n = i >> 4, q = i & 15;
        float4 v = (n < nRows)
            ? reinterpret_cast<const float4*>(p)[(size_t)(base + n) * 16 + q]
            : make_float4(0.f, 0.f, 0.f, 0.f);
        sT[4 * q + 0][n] = v.x;
        sT[4 * q + 1][n] = v.y;
        sT[4 * q + 2][n] = v.z;
        sT[4 * q + 3][n] = v.w;
    }
}

// ---------------------------------------------------------------------------
// K1: node precompute  h1 = X@Wu,  hu2 = X@Wcu,  hv2 = S@WcvS + X@WcvX
// ---------------------------------------------------------------------------
__global__ __launch_bounds__(256) void k_node_pre(const float* __restrict__ S,
                                                  const float* __restrict__ X,
                                                  const float* __restrict__ Wu,
                                                  int N) {
    extern __shared__ float sm[];
    float (*sXT)[65] = (float(*)[65])sm;              // 4160
    float (*sST)[65] = (float(*)[65])(sm + 4160);     // 4160
    float* sWcu  = sm + 8320;                          // 4096
    float* sWcvS = sm + 12416;                         // 4096
    float* sWcvX = sm + 16512;                         // 4096
    float* sWu   = sm + 20608;                         // 4096 -> 24704 total

    int tid = threadIdx.x;
    int base = blockIdx.x * 64;
    int nN = N - base; if (nN > 64) nN = 64;

    for (int i = tid; i < D * D; i += 256) {
        sWcu[i]  = g_Wcu[i];
        sWcvS[i] = g_Wcv[i];
        sWcvX[i] = g_Wcv[D * D + i];
        sWu[i]   = Wu[i];
    }
    load_tile_T(sXT, X, base, nN, tid);
    load_tile_T(sST, S, base, nN, tid);
    __syncthreads();

    int tx = tid & 15, ty = tid >> 4;
    float accU[4][4] = {}, accV[4][4] = {}, accH[4][4] = {};
    #pragma unroll 8
    for (int k = 0; k < D; k++) {
        float x0 = sXT[k][ty * 4 + 0], x1 = sXT[k][ty * 4 + 1];
        float x2 = sXT[k][ty * 4 + 2], x3 = sXT[k][ty * 4 + 3];
        float s0 = sST[k][ty * 4 + 0], s1 = sST[k][ty * 4 + 1];
        float s2 = sST[k][ty * 4 + 2], s3 = sST[k][ty * 4 + 3];
        float4 bu = *reinterpret_cast<const float4*>(&sWcu[k * D + tx * 4]);
        float4 bs = *reinterpret_cast<const float4*>(&sWcvS[k * D + tx * 4]);
        float4 bx = *reinterpret_cast<const float4*>(&sWcvX[k * D + tx * 4]);
        float4 bh = *reinterpret_cast<const float4*>(&sWu[k * D + tx * 4]);
        accU[0][0] += x0*bu.x; accU[0][1] += x0*bu.y; accU[0][2] += x0*bu.z; accU[0][3] += x0*bu.w;
        accU[1][0] += x1*bu.x; accU[1][1] += x1*bu.y; accU[1][2] += x1*bu.z; accU[1][3] += x1*bu.w;
        accU[2][0] += x2*bu.x; accU[2][1] += x2*bu.y; accU[2][2] += x2*bu.z; accU[2][3] += x2*bu.w;
        accU[3][0] += x3*bu.x; accU[3][1] += x3*bu.y; accU[3][2] += x3*bu.z; accU[3][3] += x3*bu.w;
        accH[0][0] += x0*bh.x; accH[0][1] += x0*bh.y; accH[0][2] += x0*bh.z; accH[0][3] += x0*bh.w;
        accH[1][0] += x1*bh.x; accH[1][1] += x1*bh.y; accH[1][2] += x1*bh.z; accH[1][3] += x1*bh.w;
        accH[2][0] += x2*bh.x; accH[2][1] += x2*bh.y; accH[2][2] += x2*bh.z; accH[2][3] += x2*bh.w;
        accH[3][0] += x3*bh.x; accH[3][1] += x3*bh.y; accH[3][2] += x3*bh.z; accH[3][3] += x3*bh.w;
        accV[0][0] += s0*bs.x + x0*bx.x; accV[0][1] += s0*bs.y + x0*bx.y;
        accV[0][2] += s0*bs.z + x0*bx.z; accV[0][3] += s0*bs.w + x0*bx.w;
        accV[1][0] += s1*bs.x + x1*bx.x; accV[1][1] += s1*bs.y + x1*bx.y;
        accV[1][2] += s1*bs.z + x1*bx.z; accV[1][3] += s1*bs.w + x1*bx.w;
        accV[2][0] += s2*bs.x + x2*bx.x; accV[2][1] += s2*bs.y + x2*bx.y;
        accV[2][2] += s2*bs.z + x2*bx.z; accV[2][3] += s2*bs.w + x2*bx.w;
        accV[3][0] += s3*bs.x + x3*bx.x; accV[3][1] += s3*bs.y + x3*bx.y;
        accV[3][2] += s3*bs.z + x3*bx.z; accV[3][3] += s3*bs.w + x3*bx.w;
    }

    #pragma unroll
    for (int r = 0; r < 4; r++) {
        int n = ty * 4 + r;
        if (n >= nN) continue;
        size_t o = (size_t)(base + n) * 16 + tx;
        reinterpret_cast<float4*>(g_hu2)[o] =
            make_float4(accU[r][0], accU[r][1], accU[r][2], accU[r][3]);
        reinterpret_cast<float4*>(g_hv2)[o] =
            make_float4(accV[r][0], accV[r][1], accV[r][2], accV[r][3]);
        reinterpret_cast<float4*>(g_h1)[o] =
            make_float4(accH[r][0], accH[r][1], accH[r][2], accH[r][3]);
    }
}

// ---------------------------------------------------------------------------
// K_edge v11: persistent CTAs + (mg, nquad) warp remap.
//  - weights loaded to smem ONCE per block (separate sB, no aliasing)
//  - warp = (m-group of 32 edges, n-quad of 2 ntiles): B-fragment smem
//    re-reads drop 4x -> 2x (B LDS was the largest L1 wavefront stream)
//  - single sOut buffer, sequential staging: stage e1 -> scatter ->
//    stage e_out -> epilogue (4 syncs/tile)
// smem 69.1KB -> 3 CTAs/SM.
// ---------------------------------------------------------------------------
#define SE_PITCH 68
#define SO_PITCH 72
__global__ __launch_bounds__(256)
void k_edge(const float* __restrict__ edge_in,
            const int* __restrict__ src,
            const int* __restrict__ dst,
            const float* __restrict__ bias_e,
            float* __restrict__ e_out,
            int E, int nTiles) {
    extern __shared__ float sm[];
    float* sE   = sm;                            // 4352 floats
    float* sB   = sm + 64 * SE_PITCH;            // 8192 floats
    float* sOut = sB + 8192;                     // 4608 floats
    int* sSrc = (int*)(sOut + 64 * SO_PITCH);    // 64
    int* sDst = sSrc + 64;                       // 64

    int tid = threadIdx.x;

    // weights: once per block
    {
        const float4* gW = reinterpret_cast<const float4*>(g_Wmma);
        float4* sB4 = reinterpret_cast<float4*>(sB);
        #pragma unroll
        for (int it = 0; it < 8; it++)
            sB4[tid + it * 256] = gW[tid + it * 256];
    }

    int wid = tid >> 5, lane = tid & 31;
    int gid = lane >> 2, tig = lane & 3;
    int mg = wid & 1;            // m-group: 32 edges
    int nquad = wid >> 1;        // 2 ntiles: nquad*2, nquad*2+1
    int em0 = mg * 32, em1 = mg * 32 + 16;

    const float4* b4  = reinterpret_cast<const float4*>(bias_e);
    const float4* h14 = reinterpret_cast<const float4*>(g_h1);
    const float4* hu4 = reinterpret_cast<const float4*>(g_hu2);
    const float4* hv4 = reinterpret_cast<const float4*>(g_hv2);

    for (int tile = blockIdx.x; tile < nTiles; tile += gridDim.x) {
        int ebase = tile * 64;
        int nE = E - ebase; if (nE > 64) nE = 64;

        // edge tile (64 x 64), edge-major
        #pragma unroll
        for (int it = 0; it < 4; it++) {
            int i = tid + it * 256;
            int e = i >> 4, q = i & 15;
            float4 v = (e < nE)
                ? reinterpret_cast<const float4*>(edge_in)[(size_t)(ebase + e) * 16 + q]
                : make_float4(0.f, 0.f, 0.f, 0.f);
            *reinterpret_cast<float4*>(&sE[e * SE_PITCH + 4 * q]) = v;
        }
        if (tid < 64) {
            sSrc[tid] = (tid < nE) ? src[ebase + tid] : 0;
            sDst[tid] = (tid < nE) ? dst[ebase + tid] : 0;
        }
        __syncthreads();   // (A) tile ready; also fences prev-iter sOut reads

        if (tid < 64 && tid < nE) atomicAdd(g_deg + sDst[tid], 1.0f);

        // ---- dual tf32 mma, 2 m-tiles x 2 ntiles per warp ----
        float acc[2][2][4], acc2[2][2][4];
        #pragma unroll
        for (int mt = 0; mt < 2; mt++)
            #pragma unroll
            for (int nt = 0; nt < 2; nt++)
                #pragma unroll
                for (int r = 0; r < 4; r++) {
                    acc[mt][nt][r] = 0.f;
                    acc2[mt][nt][r] = 0.f;
                }

        const float* r00 = &sE[(em0 + gid) * SE_PITCH];
        const float* r01 = &sE[(em0 + gid + 8) * SE_PITCH];
        const float* r10 = &sE[(em1 + gid) * SE_PITCH];
        const float* r11 = &sE[(em1 + gid + 8) * SE_PITCH];
        #pragma unroll
        for (int ks = 0; ks < 8; ks++) {
            int k0 = ks * 8 + tig;
            uint32_t a0, a1, a2, a3, a4, a5, a6, a7;
            asm("cvt.rna.tf32.f32 %0, %1;" : "=r"(a0) : "f"(r00[k0]));
            asm("cvt.rna.tf32.f32 %0, %1;" : "=r"(a1) : "f"(r01[k0]));
            asm("cvt.rna.tf32.f32 %0, %1;" : "=r"(a2) : "f"(r00[k0 + 4]));
            asm("cvt.rna.tf32.f32 %0, %1;" : "=r"(a3) : "f"(r01[k0 + 4]));
            asm("cvt.rna.tf32.f32 %0, %1;" : "=r"(a4) : "f"(r10[k0]));
            asm("cvt.rna.tf32.f32 %0, %1;" : "=r"(a5) : "f"(r11[k0]));
            asm("cvt.rna.tf32.f32 %0, %1;" : "=r"(a6) : "f"(r10[k0 + 4]));
            asm("cvt.rna.tf32.f32 %0, %1;" : "=r"(a7) : "f"(r11[k0 + 4]));
            #pragma unroll
            for (int nt = 0; nt < 2; nt++) {
                int ntile = nquad * 2 + nt;
                int boff = ((ks * 8 + ntile) * 32 + lane) * 2;
                float2 b = *reinterpret_cast<const float2*>(&sB[boff]);
                uint32_t b0 = __float_as_uint(b.x), b1 = __float_as_uint(b.y);
                asm volatile(
                    "mma.sync.aligned.m16n8k8.row.col.f32.tf32.tf32.f32 "
                    "{%0,%1,%2,%3}, {%4,%5,%6,%7}, {%8,%9}, {%0,%1,%2,%3};"
                    : "+f"(acc[0][nt][0]), "+f"(acc[0][nt][1]),
                      "+f"(acc[0][nt][2]), "+f"(acc[0][nt][3])
                    : "r"(a0), "r"(a1), "r"(a2), "r"(a3), "r"(b0), "r"(b1));
                asm volatile(
                    "mma.sync.aligned.m16n8k8.row.col.f32.tf32.tf32.f32 "
                    "{%0,%1,%2,%3}, {%4,%5,%6,%7}, {%8,%9}, {%0,%1,%2,%3};"
                    : "+f"(acc[1][nt][0]), "+f"(acc[1][nt][1]),
                      "+f"(acc[1][nt][2]), "+f"(acc[1][nt][3])
                    : "r"(a4), "r"(a5), "r"(a6), "r"(a7), "r"(b0), "r"(b1));
                float2 c = *reinterpret_cast<const float2*>(&sB[4096 + boff]);
                uint32_t c0 = __float_as_uint(c.x), c1 = __float_as_uint(c.y);
                asm volatile(
                    "mma.sync.aligned.m16n8k8.row.col.f32.tf32.tf32.f32 "
                    "{%0,%1,%2,%3}, {%4,%5,%6,%7}, {%8,%9}, {%0,%1,%2,%3};"
                    : "+f"(acc2[0][nt][0]), "+f"(acc2[0][nt][1]),
                      "+f"(acc2[0][nt][2]), "+f"(acc2[0][nt][3])
                    : "r"(a0), "r"(a1), "r"(a2), "r"(a3), "r"(c0), "r"(c1));
                asm volatile(
                    "mma.sync.aligned.m16n8k8.row.col.f32.tf32.tf32.f32 "
                    "{%0,%1,%2,%3}, {%4,%5,%6,%7}, {%8,%9}, {%0,%1,%2,%3};"
                    : "+f"(acc2[1][nt][0]), "+f"(acc2[1][nt][1]),
                      "+f"(acc2[1][nt][2]), "+f"(acc2[1][nt][3])
                    : "r"(a4), "r"(a5), "r"(a6), "r"(a7), "r"(c0), "r"(c1));
            }
        }

        // stage e1 (acc2) into sOut
        #pragma unroll
        for (int mt = 0; mt < 2; mt++) {
            int e0 = (mt ? em1 : em0) + gid, e1r = e0 + 8;
            #pragma unroll
            for (int nt = 0; nt < 2; nt++) {
                int n = (nquad * 2 + nt) * 8 + 2 * tig;
                *reinterpret_cast<float2*>(&sOut[e0 * SO_PITCH + n]) =
                    make_float2(acc2[mt][nt][0], acc2[mt][nt][1]);
                *reinterpret_cast<float2*>(&sOut[e1r * SO_PITCH + n]) =
                    make_float2(acc2[mt][nt][2], acc2[mt][nt][3]);
            }
        }
        __syncthreads();   // (B)

        // scatter: g_agg[dst] += h1[src] + e1
        #pragma unroll
        for (int it = 0; it < 4; it++) {
            int i = tid + it * 256;
            int e = i >> 4, q = i & 15;
            if (e < nE) {
                int s = sSrc[e], d2 = sDst[e];
                float4 e1v = *reinterpret_cast<const float4*>(&sOut[e * SO_PITCH + 4 * q]);
                float4 h1v = __ldg(h14 + (size_t)s * 16 + q);
                float* a = g_agg + (size_t)d2 * D + q * 4;
                asm volatile("red.global.add.v4.f32 [%0], {%1,%2,%3,%4};"
                             :: "l"(a),
                                "f"(h1v.x + e1v.x), "f"(h1v.y + e1v.y),
                                "f"(h1v.z + e1v.z), "f"(h1v.w + e1v.w)
                             : "memory");
            }
        }
        __syncthreads();   // (C)

        // stage e_out (acc) into sOut
        #pragma unroll
        for (int mt = 0; mt < 2; mt++) {
            int e0 = (mt ? em1 : em0) + gid, e1r = e0 + 8;
            #pragma unroll
            for (int nt = 0; nt < 2; nt++) {
                int n = (nquad * 2 + nt) * 8 + 2 * tig;
                *reinterpret_cast<float2*>(&sOut[e0 * SO_PITCH + n]) =
                    make_float2(acc[mt][nt][0], acc[mt][nt][1]);
                *reinterpret_cast<float2*>(&sOut[e1r * SO_PITCH + n]) =
                    make_float2(acc[mt][nt][2], acc[mt][nt][3]);
            }
        }
        __syncthreads();   // (D)

        // epilogue: e_out = acc + hu2[src] + hv2[dst] + bias
        #pragma unroll
        for (int it = 0; it < 4; it++) {
            int i = tid + it * 256;
            int e = i >> 4, q = i & 15;
            if (e < nE) {
                int s = sSrc[e], d2 = sDst[e];
                float4 av = *reinterpret_cast<const float4*>(&sOut[e * SO_PITCH + 4 * q]);
                float4 hu = __ldg(hu4 + (size_t)s  * 16 + q);
                float4 hv = __ldg(hv4 + (size_t)d2 * 16 + q);
                float4 bb = __ldg(b4 + q);
                reinterpret_cast<float4*>(e_out)[(size_t)(ebase + e) * 16 + q] =
                    make_float4(av.x + hu.x + hv.x + bb.x, av.y + hu.y + hv.y + bb.y,
                                av.z + hu.z + hv.z + bb.z, av.w + hu.w + hv.w + bb.w);
            }
        }
    }
}

// ---------------------------------------------------------------------------
// K2: single-phase — hn comes straight from g_agg/deg:
//     h_out = S@Wv0 + X@Wv1 + (g_agg/max(deg,1))@Wv2 + bias_n
// ---------------------------------------------------------------------------
__global__ __launch_bounds__(256) void k_node_out(const float* __restrict__ S,
                                                  const float* __restrict__ X,
                                                  const float* __restrict__ Wv,
                                                  const float* __restrict__ bias_n,
                                                  float* __restrict__ h_out,
                                                  int N) {
    extern __shared__ float sm[];
    float (*sST)[65] = (float(*)[65])sm;                // 0..4160
    float (*sXT)[65] = (float(*)[65])(sm + 4160);       // ..8320
    float (*sHT)[65] = (float(*)[65])(sm + 8320);       // ..12480
    float* sWv = sm + 12480;                             // ..24768

    int tid = threadIdx.x;
    int base = blockIdx.x * 64;
    int nN = N - base; if (nN > 64) nN = 64;
    int tx = tid & 15, ty = tid >> 4;

    for (int i = tid; i < 3 * D * D; i += 256)
        sWv[i] = Wv[i];
    load_tile_T(sST, S, base, nN, tid);
    load_tile_T(sXT, X, base, nN, tid);
    // hn tile: load g_agg scaled by 1/max(deg,1), transposed
    #pragma unroll
    for (int it = 0; it < 4; it++) {
        int i = tid + it * 256;
        int n = i >> 4, q = i & 15;
        float4 v = make_float4(0.f, 0.f, 0.f, 0.f);
        if (n < nN) {
            v = reinterpret_cast<const float4*>(g_agg)[(size_t)(base + n) * 16 + q];
            float inv = 1.0f / fmaxf(g_deg[base + n], 1.0f);
            v.x *= inv; v.y *= inv; v.z *= inv; v.w *= inv;
        }
        sHT[4 * q + 0][n] = v.x;
        sHT[4 * q + 1][n] = v.y;
        sHT[4 * q + 2][n] = v.z;
        sHT[4 * q + 3][n] = v.w;
    }
    __syncthreads();

    float4 bb = reinterpret_cast<const float4*>(bias_n)[tx];
    float acc[4][4];
    #pragma unroll
    for (int r = 0; r < 4; r++) {
        acc[r][0] = bb.x; acc[r][1] = bb.y; acc[r][2] = bb.z; acc[r][3] = bb.w;
    }

    #pragma unroll 8
    for (int k = 0; k < D; k++) {
        float4 wS = *reinterpret_cast<const float4*>(&sWv[k * D + tx * 4]);
        float4 wX = *reinterpret_cast<const float4*>(&sWv[(D + k) * D + tx * 4]);
        float4 wH = *reinterpret_cast<const float4*>(&sWv[(2 * D + k) * D + tx * 4]);
        #pragma unroll
        for (int r = 0; r < 4; r++) {
            float s = sST[k][ty * 4 + r];
            float x = sXT[k][ty * 4 + r];
            float h = sHT[k][ty * 4 + r];
            acc[r][0] += s * wS.x + x * wX.x + h * wH.x;
            acc[r][1] += s * wS.y + x * wX.y + h * wH.y;
            acc[r][2] += s * wS.z + x * wX.z + h * wH.z;
            acc[r][3] += s * wS.w + x * wX.w + h * wH.w;
        }
    }

    #pragma unroll
    for (int r = 0; r < 4; r++) {
        int n = ty * 4 + r;
        if (n >= nN) continue;
        reinterpret_cast<float4*>(h_out)[(size_t)(base + n) * 16 + tx] =
            make_float4(acc[r][0], acc[r][1], acc[r][2], acc[r][3]);
    }
}

// ---------------------------------------------------------------------------
extern "C" void kernel_launch(void* const* d_in, const int* in_sizes, int n_in,
                              void* d_out, int out_size) {
    const float* S      = (const float*)d_in[0];
    const float* X      = (const float*)d_in[1];
    const float* Ein    = (const float*)d_in[2];
    const int*   src    = (const int*)d_in[3];
    const int*   dst    = (const int*)d_in[4];
    const float* Wn2n_u = (const float*)d_in[5];
    const float* Wn2n_v = (const float*)d_in[6];
    const float* We2n   = (const float*)d_in[7];
    const float* bias_n = (const float*)d_in[8];
    const float* Wn2e_u = (const float*)d_in[9];
    const float* Wn2e_v = (const float*)d_in[10];
    const float* We2e   = (const float*)d_in[11];
    const float* bias_e = (const float*)d_in[12];

    int N = in_sizes[1] / D;
    int E = in_sizes[3];
    float* h_out = (float*)d_out;
    float* e_out = h_out + (size_t)N * D;

    const int SM_PRE  = 24704 * 4;                                   // 98816 B
    const int SM_OUT  = 24768 * 4;                                   // 99072 B
    const int SM_EDGE = (64 * SE_PITCH + 8192 + 64 * SO_PITCH) * 4
                        + 128 * 4;                                   // 69120 B

    cudaFuncSetAttribute(k_node_pre, cudaFuncAttributeMaxDynamicSharedMemorySize, SM_PRE);
    cudaFuncSetAttribute(k_node_out, cudaFuncAttributeMaxDynamicSharedMemorySize, SM_OUT);
    cudaFuncSetAttribute(k_edge,     cudaFuncAttributeMaxDynamicSharedMemorySize, SM_EDGE);

    int nBlk = (N + 63) / 64;
    int nTiles = (E + 63) / 64;
    int edgeGrid = 148 * 3;
    if (edgeGrid > nTiles) edgeGrid = nTiles;

    k_zero<<<(N * D / 4 + 255) / 256, 256>>>(N);
    k_wprep<<<(3 * D * D + 2 * 2048 + 255) / 256, 256>>>(Wn2e_u, Wn2e_v, We2e, We2n);
    k_node_pre<<<nBlk, 256, SM_PRE>>>(S, X, Wn2n_u, N);
    k_edge<<<edgeGrid, 256, SM_EDGE>>>(Ein, src, dst, bias_e, e_out, E, nTiles);
    k_node_out<<<nBlk, 256, SM_OUT>>>(S, X, Wn2n_v, bias_n, h_out, N);
}

// round 16
// speedup vs baseline: 1.0068x; 1.0068x over previous
#include <cuda_runtime.h>
#include <cuda_bf16.h>
#include <cstdint>

#define D 64
#define MAXN 50176

// Scratch (static device globals — allocation-free). Referenced ONLY in
// device code (host-side symbol is an ATS-readable shadow — Round-2 bug).
__device__ float g_agg[MAXN * D];    // sum over dst of (h1[src] + e1)
__device__ float g_deg[MAXN];
__device__ float g_h1[MAXN * D];     // X @ Wn2n_u
__device__ float g_hu2[MAXN * D];    // X @ (W_n2e_u @ W_e2e_bot)
__device__ float g_hv2[MAXN * D];    // [S,X] @ (W_n2e_v @ W_e2e_bot)
__device__ float g_Wcu[D * D];
__device__ float g_Wcv[2 * D * D];
// tf32 B fragments, 2 sets: [0:4096) We2e_top, [4096:8192) We2n
// layout per set: [kstep 8][ntile 8][lane 32][2]
__device__ float g_Wmma[2 * 8 * 8 * 32 * 2];

// ---------------------------------------------------------------------------
__global__ void k_zero(int N) {
    int i = blockIdx.x * blockDim.x + threadIdx.x;
    int nv = N * D / 4;
    if (i < nv)
        reinterpret_cast<float4*>(g_agg)[i] = make_float4(0.f, 0.f, 0.f, 0.f);
    if (i < N) g_deg[i] = 0.0f;
}

// ---------------------------------------------------------------------------
// K0b: composite weights Wcu, Wcv + tf32 fragments of We2e_top and We2n
// ---------------------------------------------------------------------------
__global__ void k_wprep(const float* __restrict__ Wn2e_u,
                        const float* __restrict__ Wn2e_v,
                        const float* __restrict__ We2e,
                        const float* __restrict__ We2n) {
    int idx = blockIdx.x * blockDim.x + threadIdx.x;
    if (idx < D * D) {
        int r = idx >> 6, j = idx & 63;
        float s = 0.0f;
        #pragma unroll 8
        for (int t = 0; t < D; t++)
            s += __ldg(Wn2e_u + r * D + t) * __ldg(We2e + (D + t) * D + j);
        g_Wcu[idx] = s;
    } else if (idx < 3 * D * D) {
        int i2 = idx - D * D;
        int r = i2 >> 6, j = i2 & 63;
        float s = 0.0f;
        #pragma unroll 8
        for (int t = 0; t < D; t++)
            s += __ldg(Wn2e_v + r * D + t) * __ldg(We2e + (D + t) * D + j);
        g_Wcv[i2] = s;
    } else if (idx < 3 * D * D + 2 * 2048) {
        int i = idx - 3 * D * D;               // 0..4095
        int set = i >> 11;                     // 0: We2e_top, 1: We2n
        int j = i & 2047;
        int lane = j & 31, nt = (j >> 5) & 7, ks = j >> 8;
        int gid = lane >> 2, tig = lane & 3;
        const float* W = set ? We2n : We2e;    // We2e rows 0..63 = top
        float w0 = W[(ks * 8 + tig) * D + nt * 8 + gid];
        float w1 = W[(ks * 8 + tig + 4) * D + nt * 8 + gid];
        uint32_t t0, t1;
        asm("cvt.rna.tf32.f32 %0, %1;" : "=r"(t0) : "f"(w0));
        asm("cvt.rna.tf32.f32 %0, %1;" : "=r"(t1) : "f"(w1));
        g_Wmma[i * 2 + 0] = __uint_as_float(t0);
        g_Wmma[i * 2 + 1] = __uint_as_float(t1);
    }
}

// ---------------------------------------------------------------------------
// Tile loader: 64 rows x 64 feats transposed (node kernels)
// ---------------------------------------------------------------------------
__device__ __forceinline__ void load_tile_T(float (*sT)[65],
                                            const float* __restrict__ p,
                                            int base, int nRows, int tid) {
    for (int i = tid; i < 64 * 16; i += 256) {
        int n = i >> 4, q = i & 15;
        float4 v = (n < nRows)
            ? reinterpret_cast<const float4*>(p)[(size_t)(base + n) * 16 + q]
            : make_float4(0.f, 0.f, 0.f, 0.f);
        sT[4 * q + 0][n] = v.x;
        sT[4 * q + 1][n] = v.y;
        sT[4 * q + 2][n] = v.z;
        sT[4 * q + 3][n] = v.w;
    }
}

// ---------------------------------------------------------------------------
// K1: node precompute  h1 = X@Wu,  hu2 = X@Wcu,  hv2 = S@WcvS + X@WcvX
// Weights via __ldg (L1-resident broadcast; node-kernel L1 has headroom) —
// smem 33.3KB (tiles only) for higher occupancy.
// ---------------------------------------------------------------------------
__global__ __launch_bounds__(256) void k_node_pre(const float* __restrict__ S,
                                                  const float* __restrict__ X,
                                                  const float* __restrict__ Wu,
                                                  int N) {
    extern __shared__ float sm[];
    float (*sXT)[65] = (float(*)[65])sm;              // 4160
    float (*sST)[65] = (float(*)[65])(sm + 4160);     // 4160 -> 8320 total

    int tid = threadIdx.x;
    int base = blockIdx.x * 64;
    int nN = N - base; if (nN > 64) nN = 64;

    load_tile_T(sXT, X, base, nN, tid);
    load_tile_T(sST, S, base, nN, tid);
    __syncthreads();

    const float4* Wcu4  = reinterpret_cast<const float4*>(g_Wcu);
    const float4* WcvS4 = reinterpret_cast<const float4*>(g_Wcv);
    const float4* WcvX4 = reinterpret_cast<const float4*>(g_Wcv + D * D);
    const float4* Wu4   = reinterpret_cast<const float4*>(Wu);

    int tx = tid & 15, ty = tid >> 4;
    float accU[4][4] = {}, accV[4][4] = {}, accH[4][4] = {};
    #pragma unroll 8
    for (int k = 0; k < D; k++) {
        float x0 = sXT[k][ty * 4 + 0], x1 = sXT[k][ty * 4 + 1];
        float x2 = sXT[k][ty * 4 + 2], x3 = sXT[k][ty * 4 + 3];
        float s0 = sST[k][ty * 4 + 0], s1 = sST[k][ty * 4 + 1];
        float s2 = sST[k][ty * 4 + 2], s3 = sST[k][ty * 4 + 3];
        float4 bu = __ldg(Wcu4  + k * 16 + tx);
        float4 bs = __ldg(WcvS4 + k * 16 + tx);
        float4 bx = __ldg(WcvX4 + k * 16 + tx);
        float4 bh = __ldg(Wu4   + k * 16 + tx);
        accU[0][0] += x0*bu.x; accU[0][1] += x0*bu.y; accU[0][2] += x0*bu.z; accU[0][3] += x0*bu.w;
        accU[1][0] += x1*bu.x; accU[1][1] += x1*bu.y; accU[1][2] += x1*bu.z; accU[1][3] += x1*bu.w;
        accU[2][0] += x2*bu.x; accU[2][1] += x2*bu.y; accU[2][2] += x2*bu.z; accU[2][3] += x2*bu.w;
        accU[3][0] += x3*bu.x; accU[3][1] += x3*bu.y; accU[3][2] += x3*bu.z; accU[3][3] += x3*bu.w;
        accH[0][0] += x0*bh.x; accH[0][1] += x0*bh.y; accH[0][2] += x0*bh.z; accH[0][3] += x0*bh.w;
        accH[1][0] += x1*bh.x; accH[1][1] += x1*bh.y; accH[1][2] += x1*bh.z; accH[1][3] += x1*bh.w;
        accH[2][0] += x2*bh.x; accH[2][1] += x2*bh.y; accH[2][2] += x2*bh.z; accH[2][3] += x2*bh.w;
        accH[3][0] += x3*bh.x; accH[3][1] += x3*bh.y; accH[3][2] += x3*bh.z; accH[3][3] += x3*bh.w;
        accV[0][0] += s0*bs.x + x0*bx.x; accV[0][1] += s0*bs.y + x0*bx.y;
        accV[0][2] += s0*bs.z + x0*bx.z; accV[0][3] += s0*bs.w + x0*bx.w;
        accV[1][0] += s1*bs.x + x1*bx.x; accV[1][1] += s1*bs.y + x1*bx.y;
        accV[1][2] += s1*bs.z + x1*bx.z; accV[1][3] += s1*bs.w + x1*bx.w;
        accV[2][0] += s2*bs.x + x2*bx.x; accV[2][1] += s2*bs.y + x2*bx.y;
        accV[2][2] += s2*bs.z + x2*bx.z; accV[2][3] += s2*bs.w + x2*bx.w;
        accV[3][0] += s3*bs.x + x3*bx.x; accV[3][1] += s3*bs.y + x3*bx.y;
        accV[3][2] += s3*bs.z + x3*bx.z; accV[3][3] += s3*bs.w + x3*bx.w;
    }

    #pragma unroll
    for (int r = 0; r < 4; r++) {
        int n = ty * 4 + r;
        if (n >= nN) continue;
        size_t o = (size_t)(base + n) * 16 + tx;
        reinterpret_cast<float4*>(g_hu2)[o] =
            make_float4(accU[r][0], accU[r][1], accU[r][2], accU[r][3]);
        reinterpret_cast<float4*>(g_hv2)[o] =
            make_float4(accV[r][0], accV[r][1], accV[r][2], accV[r][3]);
        reinterpret_cast<float4*>(g_h1)[o] =
            make_float4(accH[r][0], accH[r][1], accH[r][2], accH[r][3]);
    }
}

// ---------------------------------------------------------------------------
// K_edge v10 (EXACT R14 revert — proven 203.4us, deterministic 2.87e-4):
// dual tf32 mma with SMEM weights, single staging phase into sOut0/sOut1
// aliased over the dead sB region, one fused final pass (scatter + epilogue).
// 3 syncthreads. smem 54.8KB -> 4 CTAs/SM.
// ---------------------------------------------------------------------------
#define SE_PITCH 68
#define SO_PITCH 72
__global__ __launch_bounds__(256)
void k_edge(const float* __restrict__ edge_in,
            const int* __restrict__ src,
            const int* __restrict__ dst,
            const float* __restrict__ bias_e,
            float* __restrict__ e_out,
            int E) {
    extern __shared__ float sm[];
    float* sE = sm;                             // 4352 floats
    float* sB = sm + 64 * SE_PITCH;             // alias region: 9216 floats
    float* sOut0 = sB;                          // 64*72 = 4608 (e_out acc)
    float* sOut1 = sB + 64 * SO_PITCH;          // 64*72 = 4608 (e1 acc)
    int* sSrc = (int*)(sB + 2 * 64 * SO_PITCH); // 64
    int* sDst = sSrc + 64;                      // 64

    int tid = threadIdx.x;
    int ebase = blockIdx.x * 64;
    int nE = E - ebase; if (nE > 64) nE = 64;

    // weights: vectorized float4 copy (2048 float4) into first 8192 of alias
    {
        const float4* gW = reinterpret_cast<const float4*>(g_Wmma);
        float4* sB4 = reinterpret_cast<float4*>(sB);
        #pragma unroll
        for (int it = 0; it < 8; it++)
            sB4[tid + it * 256] = gW[tid + it * 256];
    }

    // edge tile (64 x 64), edge-major
    #pragma unroll
    for (int it = 0; it < 4; it++) {
        int i = tid + it * 256;
        int e = i >> 4, q = i & 15;
        float4 v = (e < nE)
            ? reinterpret_cast<const float4*>(edge_in)[(size_t)(ebase + e) * 16 + q]
            : make_float4(0.f, 0.f, 0.f, 0.f);
        *reinterpret_cast<float4*>(&sE[e * SE_PITCH + 4 * q]) = v;
    }
    if (tid < 64) {
        sSrc[tid] = (tid < nE) ? src[ebase + tid] : 0;
        sDst[tid] = (tid < nE) ? dst[ebase + tid] : 0;
    }
    __syncthreads();

    if (tid < 64 && tid < nE) atomicAdd(g_deg + sDst[tid], 1.0f);

    int wid = tid >> 5, lane = tid & 31;
    int gid = lane >> 2, tig = lane & 3;
    int mw = wid & 3;            // m-tile (16 edges)
    int nhalf = wid >> 2;        // 0: n 0..31, 1: n 32..63
    int ew = mw * 16;

    // ---- dual tf32 mma: acc (e_out via We2e_top), acc2 (e1 via We2n) ----
    float acc[4][4], acc2[4][4];
    #pragma unroll
    for (int nt = 0; nt < 4; nt++) {
        acc[nt][0] = 0.f; acc[nt][1] = 0.f; acc[nt][2] = 0.f; acc[nt][3] = 0.f;
        acc2[nt][0] = 0.f; acc2[nt][1] = 0.f; acc2[nt][2] = 0.f; acc2[nt][3] = 0.f;
    }

    const float* rowA0 = &sE[(ew + gid) * SE_PITCH];
    const float* rowA1 = &sE[(ew + gid + 8) * SE_PITCH];
    #pragma unroll
    for (int ks = 0; ks < 8; ks++) {
        int k0 = ks * 8 + tig;
        uint32_t a0, a1, a2, a3;
        asm("cvt.rna.tf32.f32 %0, %1;" : "=r"(a0) : "f"(rowA0[k0]));
        asm("cvt.rna.tf32.f32 %0, %1;" : "=r"(a1) : "f"(rowA1[k0]));
        asm("cvt.rna.tf32.f32 %0, %1;" : "=r"(a2) : "f"(rowA0[k0 + 4]));
        asm("cvt.rna.tf32.f32 %0, %1;" : "=r"(a3) : "f"(rowA1[k0 + 4]));
        #pragma unroll
        for (int nt = 0; nt < 4; nt++) {
            int ntile = nhalf * 4 + nt;
            int boff = ((ks * 8 + ntile) * 32 + lane) * 2;
            float2 b = *reinterpret_cast<const float2*>(&sB[boff]);
            uint32_t b0 = __float_as_uint(b.x), b1 = __float_as_uint(b.y);
            asm volatile(
                "mma.sync.aligned.m16n8k8.row.col.f32.tf32.tf32.f32 "
                "{%0,%1,%2,%3}, {%4,%5,%6,%7}, {%8,%9}, {%0,%1,%2,%3};"
                : "+f"(acc[nt][0]), "+f"(acc[nt][1]),
                  "+f"(acc[nt][2]), "+f"(acc[nt][3])
                : "r"(a0), "r"(a1), "r"(a2), "r"(a3), "r"(b0), "r"(b1));
            float2 c = *reinterpret_cast<const float2*>(&sB[4096 + boff]);
            uint32_t c0 = __float_as_uint(c.x), c1 = __float_as_uint(c.y);
            asm volatile(
                "mma.sync.aligned.m16n8k8.row.col.f32.tf32.tf32.f32 "
                "{%0,%1,%2,%3}, {%4,%5,%6,%7}, {%8,%9}, {%0,%1,%2,%3};"
                : "+f"(acc2[nt][0]), "+f"(acc2[nt][1]),
                  "+f"(acc2[nt][2]), "+f"(acc2[nt][3])
                : "r"(a0), "r"(a1), "r"(a2), "r"(a3), "r"(c0), "r"(c1));
        }
    }
    __syncthreads();   // ALL warps done reading sB before aliasing writes

    // stage both accumulators into the alias region (pitch 72 -> 2-way max)
    {
        int e0 = ew + gid, e1r = ew + gid + 8;
        #pragma unroll
        for (int nt = 0; nt < 4; nt++) {
            int n = (nhalf * 4 + nt) * 8 + 2 * tig;
            *reinterpret_cast<float2*>(&sOut0[e0 * SO_PITCH + n]) =
                make_float2(acc[nt][0], acc[nt][1]);
            *reinterpret_cast<float2*>(&sOut0[e1r * SO_PITCH + n]) =
                make_float2(acc[nt][2], acc[nt][3]);
            *reinterpret_cast<float2*>(&sOut1[e0 * SO_PITCH + n]) =
                make_float2(acc2[nt][0], acc2[nt][1]);
            *reinterpret_cast<float2*>(&sOut1[e1r * SO_PITCH + n]) =
                make_float2(acc2[nt][2], acc2[nt][3]);
        }
    }
    __syncthreads();

    // ---- fused final pass: scatter RED(h1[src]+e1) + coalesced epilogue ----
    const float4* b4  = reinterpret_cast<const float4*>(bias_e);
    const float4* h14 = reinterpret_cast<const float4*>(g_h1);
    const float4* hu4 = reinterpret_cast<const float4*>(g_hu2);
    const float4* hv4 = reinterpret_cast<const float4*>(g_hv2);
    #pragma unroll
    for (int it = 0; it < 4; it++) {
        int i = tid + it * 256;
        int e = i >> 4, q = i & 15;
        if (e < nE) {
            int s = sSrc[e], d2 = sDst[e];
            // scatter: g_agg[dst] += h1[src] + e1
            float4 e1v = *reinterpret_cast<const float4*>(&sOut1[e * SO_PITCH + 4 * q]);
            float4 h1v = __ldg(h14 + (size_t)s * 16 + q);
            float* a = g_agg + (size_t)d2 * D + q * 4;
            asm volatile("red.global.add.v4.f32 [%0], {%1,%2,%3,%4};"
                         :: "l"(a),
                            "f"(h1v.x + e1v.x), "f"(h1v.y + e1v.y),
                            "f"(h1v.z + e1v.z), "f"(h1v.w + e1v.w)
                         : "memory");
            // epilogue: e_out = acc + hu2[src] + hv2[dst] + bias
            float4 av = *reinterpret_cast<const float4*>(&sOut0[e * SO_PITCH + 4 * q]);
            float4 hu = __ldg(hu4 + (size_t)s  * 16 + q);
            float4 hv = __ldg(hv4 + (size_t)d2 * 16 + q);
            float4 bb = __ldg(b4 + q);
            reinterpret_cast<float4*>(e_out)[(size_t)(ebase + e) * 16 + q] =
                make_float4(av.x + hu.x + hv.x + bb.x, av.y + hu.y + hv.y + bb.y,
                            av.z + hu.z + hv.z + bb.z, av.w + hu.w + hv.w + bb.w);
        }
    }
}

// ---------------------------------------------------------------------------
// K2: single-phase — hn comes straight from g_agg/deg:
//     h_out = S@Wv0 + X@Wv1 + (g_agg/max(deg,1))@Wv2 + bias_n
// Wv via __ldg — smem 49.9KB (tiles only) for 4 CTAs/SM.
// ---------------------------------------------------------------------------
__global__ __launch_bounds__(256) void k_node_out(const float* __restrict__ S,
                                                  const float* __restrict__ X,
                                                  const float* __restrict__ Wv,
                                                  const float* __restrict__ bias_n,
                                                  float* __restrict__ h_out,
                                                  int N) {
    extern __shared__ float sm[];
    float (*sST)[65] = (float(*)[65])sm;                // 0..4160
    float (*sXT)[65] = (float(*)[65])(sm + 4160);       // ..8320
    float (*sHT)[65] = (float(*)[65])(sm + 8320);       // ..12480

    int tid = threadIdx.x;
    int base = blockIdx.x * 64;
    int nN = N - base; if (nN > 64) nN = 64;
    int tx = tid & 15, ty = tid >> 4;

    load_tile_T(sST, S, base, nN, tid);
    load_tile_T(sXT, X, base, nN, tid);
    // hn tile: load g_agg scaled by 1/max(deg,1), transposed
    #pragma unroll
    for (int it = 0; it < 4; it++) {
        int i = tid + it * 256;
        int n = i >> 4, q = i & 15;
        float4 v = make_float4(0.f, 0.f, 0.f, 0.f);
        if (n < nN) {
            v = reinterpret_cast<const float4*>(g_agg)[(size_t)(base + n) * 16 + q];
            float inv = 1.0f / fmaxf(g_deg[base + n], 1.0f);
            v.x *= inv; v.y *= inv; v.z *= inv; v.w *= inv;
        }
        sHT[4 * q + 0][n] = v.x;
        sHT[4 * q + 1][n] = v.y;
        sHT[4 * q + 2][n] = v.z;
        sHT[4 * q + 3][n] = v.w;
    }
    __syncthreads();

    const float4* Wv4 = reinterpret_cast<const float4*>(Wv);
    float4 bb = reinterpret_cast<const float4*>(bias_n)[tx];
    float acc[4][4];
    #pragma unroll
    for (int r = 0; r < 4; r++) {
        acc[r][0] = bb.x; acc[r][1] = bb.y; acc[r][2] = bb.z; acc[r][3] = bb.w;
    }

    #pragma unroll 8
    for (int k = 0; k < D; k++) {
        float4 wS = __ldg(Wv4 + k * 16 + tx);
        float4 wX = __ldg(Wv4 + (D + k) * 16 + tx);
        float4 wH = __ldg(Wv4 + (2 * D + k) * 16 + tx);
        #pragma unroll
        for (int r = 0; r < 4; r++) {
            float s = sST[k][ty * 4 + r];
            float x = sXT[k][ty * 4 + r];
            float h = sHT[k][ty * 4 + r];
            acc[r][0] += s * wS.x + x * wX.x + h * wH.x;
            acc[r][1] += s * wS.y + x * wX.y + h * wH.y;
            acc[r][2] += s * wS.z + x * wX.z + h * wH.z;
            acc[r][3] += s * wS.w + x * wX.w + h * wH.w;
        }
    }

    #pragma unroll
    for (int r = 0; r < 4; r++) {
        int n = ty * 4 + r;
        if (n >= nN) continue;
        reinterpret_cast<float4*>(h_out)[(size_t)(base + n) * 16 + tx] =
            make_float4(acc[r][0], acc[r][1], acc[r][2], acc[r][3]);
    }
}

// ---------------------------------------------------------------------------
extern "C" void kernel_launch(void* const* d_in, const int* in_sizes, int n_in,
                              void* d_out, int out_size) {
    const float* S      = (const float*)d_in[0];
    const float* X      = (const float*)d_in[1];
    const float* Ein    = (const float*)d_in[2];
    const int*   src    = (const int*)d_in[3];
    const int*   dst    = (const int*)d_in[4];
    const float* Wn2n_u = (const float*)d_in[5];
    const float* Wn2n_v = (const float*)d_in[6];
    const float* We2n   = (const float*)d_in[7];
    const float* bias_n = (const float*)d_in[8];
    const float* Wn2e_u = (const float*)d_in[9];
    const float* Wn2e_v = (const float*)d_in[10];
    const float* We2e   = (const float*)d_in[11];
    const float* bias_e = (const float*)d_in[12];

    int N = in_sizes[1] / D;
    int E = in_sizes[3];
    float* h_out = (float*)d_out;
    float* e_out = h_out + (size_t)N * D;

    const int SM_PRE  = 8320 * 4;                                    // 33280 B
    const int SM_OUT  = 12480 * 4;                                   // 49920 B
    const int SM_EDGE = (64 * SE_PITCH + 2 * 64 * SO_PITCH) * 4
                        + 128 * 4;                                   // 54784 B

    cudaFuncSetAttribute(k_node_pre, cudaFuncAttributeMaxDynamicSharedMemorySize, SM_PRE);
    cudaFuncSetAttribute(k_node_out, cudaFuncAttributeMaxDynamicSharedMemorySize, SM_OUT);
    cudaFuncSetAttribute(k_edge,     cudaFuncAttributeMaxDynamicSharedMemorySize, SM_EDGE);

    int nBlk = (N + 63) / 64;
    k_zero<<<(N * D / 4 + 255) / 256, 256>>>(N);
    k_wprep<<<(3 * D * D + 2 * 2048 + 255) / 256, 256>>>(Wn2e_u, Wn2e_v, We2e, We2n);
    k_node_pre<<<nBlk, 256, SM_PRE>>>(S, X, Wn2n_u, N);
    k_edge<<<(E + 63) / 64, 256, SM_EDGE>>>(Ein, src, dst, bias_e, e_out, E);
    k_node_out<<<nBlk, 256, SM_OUT>>>(S, X, Wn2n_v, bias_n, h_out, N);
}

// round 17
// speedup vs baseline: 1.0562x; 1.0490x over previous
#include <cuda_runtime.h>
#include <cuda_bf16.h>
#include <cstdint>

#define D 64
#define MAXN 50176

// Scratch (static device globals — allocation-free). Referenced ONLY in
// device code (host-side symbol is an ATS-readable shadow — Round-2 bug).
__device__ float g_agg[MAXN * D];    // sum over dst of (h1[src] + e1)
__device__ float g_deg[MAXN];
__device__ float g_h1[MAXN * D];     // X @ Wn2n_u
__device__ float g_hu2[MAXN * D];    // X @ (W_n2e_u @ W_e2e_bot)
__device__ float g_hv2[MAXN * D];    // [S,X] @ (W_n2e_v @ W_e2e_bot)
__device__ float g_Wcu[D * D];
__device__ float g_Wcv[2 * D * D];
// tf32 B fragments, 2 sets: [0:4096) We2e_top, [4096:8192) We2n
// layout per set: [kstep 8][ntile 8][lane 32][2]
__device__ float g_Wmma[2 * 8 * 8 * 32 * 2];

// ---------------------------------------------------------------------------
// K0b: composite weights Wcu, Wcv + tf32 fragments of We2e_top and We2n
// ---------------------------------------------------------------------------
__global__ void k_wprep(const float* __restrict__ Wn2e_u,
                        const float* __restrict__ Wn2e_v,
                        const float* __restrict__ We2e,
                        const float* __restrict__ We2n) {
    int idx = blockIdx.x * blockDim.x + threadIdx.x;
    if (idx < D * D) {
        int r = idx >> 6, j = idx & 63;
        float s = 0.0f;
        #pragma unroll 8
        for (int t = 0; t < D; t++)
            s += __ldg(Wn2e_u + r * D + t) * __ldg(We2e + (D + t) * D + j);
        g_Wcu[idx] = s;
    } else if (idx < 3 * D * D) {
        int i2 = idx - D * D;
        int r = i2 >> 6, j = i2 & 63;
        float s = 0.0f;
        #pragma unroll 8
        for (int t = 0; t < D; t++)
            s += __ldg(Wn2e_v + r * D + t) * __ldg(We2e + (D + t) * D + j);
        g_Wcv[i2] = s;
    } else if (idx < 3 * D * D + 2 * 2048) {
        int i = idx - 3 * D * D;               // 0..4095
        int set = i >> 11;                     // 0: We2e_top, 1: We2n
        int j = i & 2047;
        int lane = j & 31, nt = (j >> 5) & 7, ks = j >> 8;
        int gid = lane >> 2, tig = lane & 3;
        const float* W = set ? We2n : We2e;    // We2e rows 0..63 = top
        float w0 = W[(ks * 8 + tig) * D + nt * 8 + gid];
        float w1 = W[(ks * 8 + tig + 4) * D + nt * 8 + gid];
        uint32_t t0, t1;
        asm("cvt.rna.tf32.f32 %0, %1;" : "=r"(t0) : "f"(w0));
        asm("cvt.rna.tf32.f32 %0, %1;" : "=r"(t1) : "f"(w1));
        g_Wmma[i * 2 + 0] = __uint_as_float(t0);
        g_Wmma[i * 2 + 1] = __uint_as_float(t1);
    }
}

// ---------------------------------------------------------------------------
// Tile loader: 64 rows x 64 feats transposed (node kernels)
// ---------------------------------------------------------------------------
__device__ __forceinline__ void load_tile_T(float (*sT)[65],
                                            const float* __restrict__ p,
                                            int base, int nRows, int tid) {
    for (int i = tid; i < 64 * 16; i += 256) {
        int n = i >> 4, q = i & 15;
        float4 v = (n < nRows)
            ? reinterpret_cast<const float4*>(p)[(size_t)(base + n) * 16 + q]
            : make_float4(0.f, 0.f, 0.f, 0.f);
        sT[4 * q + 0][n] = v.x;
        sT[4 * q + 1][n] = v.y;
        sT[4 * q + 2][n] = v.z;
        sT[4 * q + 3][n] = v.w;
    }
}

// ---------------------------------------------------------------------------
// K1 (R14 smem-weight version + fused zeroing of g_agg/g_deg for this
// block's node range — deletes the separate k_zero launch; ordering is safe
// because k_node_pre completes before k_edge on the same stream):
//   h1 = X@Wu,  hu2 = X@Wcu,  hv2 = S@WcvS + X@WcvX
// ---------------------------------------------------------------------------
__global__ __launch_bounds__(256) void k_node_pre(const float* __restrict__ S,
                                                  const float* __restrict__ X,
                                                  const float* __restrict__ Wu,
                                                  int N) {
    extern __shared__ float sm[];
    float (*sXT)[65] = (float(*)[65])sm;              // 4160
    float (*sST)[65] = (float(*)[65])(sm + 4160);     // 4160
    float* sWcu  = sm + 8320;                          // 4096
    float* sWcvS = sm + 12416;                         // 4096
    float* sWcvX = sm + 16512;                         // 4096
    float* sWu   = sm + 20608;                         // 4096 -> 24704 total

    int tid = threadIdx.x;
    int base = blockIdx.x * 64;
    int nN = N - base; if (nN > 64) nN = 64;

    // fused zeroing: g_agg for this block's 64 nodes (1024 float4), g_deg
    {
        float4 z = make_float4(0.f, 0.f, 0.f, 0.f);
        float4* agg4 = reinterpret_cast<float4*>(g_agg) + (size_t)base * 16;
        int nv = nN * 16;
        #pragma unroll
        for (int it = 0; it < 4; it++) {
            int i = tid + it * 256;
            if (i < nv) agg4[i] = z;
        }
        if (tid < nN) g_deg[base + tid] = 0.0f;
    }

    for (int i = tid; i < D * D; i += 256) {
        sWcu[i]  = g_Wcu[i];
        sWcvS[i] = g_Wcv[i];
        sWcvX[i] = g_Wcv[D * D + i];
        sWu[i]   = Wu[i];
    }
    load_tile_T(sXT, X, base, nN, tid);
    load_tile_T(sST, S, base, nN, tid);
    __syncthreads();

    int tx = tid & 15, ty = tid >> 4;
    float accU[4][4] = {}, accV[4][4] = {}, accH[4][4] = {};
    #pragma unroll 8
    for (int k = 0; k < D; k++) {
        float x0 = sXT[k][ty * 4 + 0], x1 = sXT[k][ty * 4 + 1];
        float x2 = sXT[k][ty * 4 + 2], x3 = sXT[k][ty * 4 + 3];
        float s0 = sST[k][ty * 4 + 0], s1 = sST[k][ty * 4 + 1];
        float s2 = sST[k][ty * 4 + 2], s3 = sST[k][ty * 4 + 3];
        float4 bu = *reinterpret_cast<const float4*>(&sWcu[k * D + tx * 4]);
        float4 bs = *reinterpret_cast<const float4*>(&sWcvS[k * D + tx * 4]);
        float4 bx = *reinterpret_cast<const float4*>(&sWcvX[k * D + tx * 4]);
        float4 bh = *reinterpret_cast<const float4*>(&sWu[k * D + tx * 4]);
        accU[0][0] += x0*bu.x; accU[0][1] += x0*bu.y; accU[0][2] += x0*bu.z; accU[0][3] += x0*bu.w;
        accU[1][0] += x1*bu.x; accU[1][1] += x1*bu.y; accU[1][2] += x1*bu.z; accU[1][3] += x1*bu.w;
        accU[2][0] += x2*bu.x; accU[2][1] += x2*bu.y; accU[2][2] += x2*bu.z; accU[2][3] += x2*bu.w;
        accU[3][0] += x3*bu.x; accU[3][1] += x3*bu.y; accU[3][2] += x3*bu.z; accU[3][3] += x3*bu.w;
        accH[0][0] += x0*bh.x; accH[0][1] += x0*bh.y; accH[0][2] += x0*bh.z; accH[0][3] += x0*bh.w;
        accH[1][0] += x1*bh.x; accH[1][1] += x1*bh.y; accH[1][2] += x1*bh.z; accH[1][3] += x1*bh.w;
        accH[2][0] += x2*bh.x; accH[2][1] += x2*bh.y; accH[2][2] += x2*bh.z; accH[2][3] += x2*bh.w;
        accH[3][0] += x3*bh.x; accH[3][1] += x3*bh.y; accH[3][2] += x3*bh.z; accH[3][3] += x3*bh.w;
        accV[0][0] += s0*bs.x + x0*bx.x; accV[0][1] += s0*bs.y + x0*bx.y;
        accV[0][2] += s0*bs.z + x0*bx.z; accV[0][3] += s0*bs.w + x0*bx.w;
        accV[1][0] += s1*bs.x + x1*bx.x; accV[1][1] += s1*bs.y + x1*bx.y;
        accV[1][2] += s1*bs.z + x1*bx.z; accV[1][3] += s1*bs.w + x1*bx.w;
        accV[2][0] += s2*bs.x + x2*bx.x; accV[2][1] += s2*bs.y + x2*bx.y;
        accV[2][2] += s2*bs.z + x2*bx.z; accV[2][3] += s2*bs.w + x2*bx.w;
        accV[3][0] += s3*bs.x + x3*bx.x; accV[3][1] += s3*bs.y + x3*bx.y;
        accV[3][2] += s3*bs.z + x3*bx.z; accV[3][3] += s3*bs.w + x3*bx.w;
    }

    #pragma unroll
    for (int r = 0; r < 4; r++) {
        int n = ty * 4 + r;
        if (n >= nN) continue;
        size_t o = (size_t)(base + n) * 16 + tx;
        reinterpret_cast<float4*>(g_hu2)[o] =
            make_float4(accU[r][0], accU[r][1], accU[r][2], accU[r][3]);
        reinterpret_cast<float4*>(g_hv2)[o] =
            make_float4(accV[r][0], accV[r][1], accV[r][2], accV[r][3]);
        reinterpret_cast<float4*>(g_h1)[o] =
            make_float4(accH[r][0], accH[r][1], accH[r][2], accH[r][3]);
    }
}

// ---------------------------------------------------------------------------
// K_edge v10 (EXACT — proven 200.6us, deterministic 2.87e-4):
// dual tf32 mma with SMEM weights, single staging phase into sOut0/sOut1
// aliased over the dead sB region, one fused final pass (scatter + epilogue).
// 3 syncthreads. smem 54.8KB -> 4 CTAs/SM.
// ---------------------------------------------------------------------------
#define SE_PITCH 68
#define SO_PITCH 72
__global__ __launch_bounds__(256)
void k_edge(const float* __restrict__ edge_in,
            const int* __restrict__ src,
            const int* __restrict__ dst,
            const float* __restrict__ bias_e,
            float* __restrict__ e_out,
            int E) {
    extern __shared__ float sm[];
    float* sE = sm;                             // 4352 floats
    float* sB = sm + 64 * SE_PITCH;             // alias region: 9216 floats
    float* sOut0 = sB;                          // 64*72 = 4608 (e_out acc)
    float* sOut1 = sB + 64 * SO_PITCH;          // 64*72 = 4608 (e1 acc)
    int* sSrc = (int*)(sB + 2 * 64 * SO_PITCH); // 64
    int* sDst = sSrc + 64;                      // 64

    int tid = threadIdx.x;
    int ebase = blockIdx.x * 64;
    int nE = E - ebase; if (nE > 64) nE = 64;

    // weights: vectorized float4 copy (2048 float4) into first 8192 of alias
    {
        const float4* gW = reinterpret_cast<const float4*>(g_Wmma);
        float4* sB4 = reinterpret_cast<float4*>(sB);
        #pragma unroll
        for (int it = 0; it < 8; it++)
            sB4[tid + it * 256] = gW[tid + it * 256];
    }

    // edge tile (64 x 64), edge-major
    #pragma unroll
    for (int it = 0; it < 4; it++) {
        int i = tid + it * 256;
        int e = i >> 4, q = i & 15;
        float4 v = (e < nE)
            ? reinterpret_cast<const float4*>(edge_in)[(size_t)(ebase + e) * 16 + q]
            : make_float4(0.f, 0.f, 0.f, 0.f);
        *reinterpret_cast<float4*>(&sE[e * SE_PITCH + 4 * q]) = v;
    }
    if (tid < 64) {
        sSrc[tid] = (tid < nE) ? src[ebase + tid] : 0;
        sDst[tid] = (tid < nE) ? dst[ebase + tid] : 0;
    }
    __syncthreads();

    if (tid < 64 && tid < nE) atomicAdd(g_deg + sDst[tid], 1.0f);

    int wid = tid >> 5, lane = tid & 31;
    int gid = lane >> 2, tig = lane & 3;
    int mw = wid & 3;            // m-tile (16 edges)
    int nhalf = wid >> 2;        // 0: n 0..31, 1: n 32..63
    int ew = mw * 16;

    // ---- dual tf32 mma: acc (e_out via We2e_top), acc2 (e1 via We2n) ----
    float acc[4][4], acc2[4][4];
    #pragma unroll
    for (int nt = 0; nt < 4; nt++) {
        acc[nt][0] = 0.f; acc[nt][1] = 0.f; acc[nt][2] = 0.f; acc[nt][3] = 0.f;
        acc2[nt][0] = 0.f; acc2[nt][1] = 0.f; acc2[nt][2] = 0.f; acc2[nt][3] = 0.f;
    }

    const float* rowA0 = &sE[(ew + gid) * SE_PITCH];
    const float* rowA1 = &sE[(ew + gid + 8) * SE_PITCH];
    #pragma unroll
    for (int ks = 0; ks < 8; ks++) {
        int k0 = ks * 8 + tig;
        uint32_t a0, a1, a2, a3;
        asm("cvt.rna.tf32.f32 %0, %1;" : "=r"(a0) : "f"(rowA0[k0]));
        asm("cvt.rna.tf32.f32 %0, %1;" : "=r"(a1) : "f"(rowA1[k0]));
        asm("cvt.rna.tf32.f32 %0, %1;" : "=r"(a2) : "f"(rowA0[k0 + 4]));
        asm("cvt.rna.tf32.f32 %0, %1;" : "=r"(a3) : "f"(rowA1[k0 + 4]));
        #pragma unroll
        for (int nt = 0; nt < 4; nt++) {
            int ntile = nhalf * 4 + nt;
            int boff = ((ks * 8 + ntile) * 32 + lane) * 2;
            float2 b = *reinterpret_cast<const float2*>(&sB[boff]);
            uint32_t b0 = __float_as_uint(b.x), b1 = __float_as_uint(b.y);
            asm volatile(
                "mma.sync.aligned.m16n8k8.row.col.f32.tf32.tf32.f32 "
                "{%0,%1,%2,%3}, {%4,%5,%6,%7}, {%8,%9}, {%0,%1,%2,%3};"
                : "+f"(acc[nt][0]), "+f"(acc[nt][1]),
                  "+f"(acc[nt][2]), "+f"(acc[nt][3])
                : "r"(a0), "r"(a1), "r"(a2), "r"(a3), "r"(b0), "r"(b1));
            float2 c = *reinterpret_cast<const float2*>(&sB[4096 + boff]);
            uint32_t c0 = __float_as_uint(c.x), c1 = __float_as_uint(c.y);
            asm volatile(
                "mma.sync.aligned.m16n8k8.row.col.f32.tf32.tf32.f32 "
                "{%0,%1,%2,%3}, {%4,%5,%6,%7}, {%8,%9}, {%0,%1,%2,%3};"
                : "+f"(acc2[nt][0]), "+f"(acc2[nt][1]),
                  "+f"(acc2[nt][2]), "+f"(acc2[nt][3])
                : "r"(a0), "r"(a1), "r"(a2), "r"(a3), "r"(c0), "r"(c1));
        }
    }
    __syncthreads();   // ALL warps done reading sB before aliasing writes

    // stage both accumulators into the alias region (pitch 72 -> 2-way max)
    {
        int e0 = ew + gid, e1r = ew + gid + 8;
        #pragma unroll
        for (int nt = 0; nt < 4; nt++) {
            int n = (nhalf * 4 + nt) * 8 + 2 * tig;
            *reinterpret_cast<float2*>(&sOut0[e0 * SO_PITCH + n]) =
                make_float2(acc[nt][0], acc[nt][1]);
            *reinterpret_cast<float2*>(&sOut0[e1r * SO_PITCH + n]) =
                make_float2(acc[nt][2], acc[nt][3]);
            *reinterpret_cast<float2*>(&sOut1[e0 * SO_PITCH + n]) =
                make_float2(acc2[nt][0], acc2[nt][1]);
            *reinterpret_cast<float2*>(&sOut1[e1r * SO_PITCH + n]) =
                make_float2(acc2[nt][2], acc2[nt][3]);
        }
    }
    __syncthreads();

    // ---- fused final pass: scatter RED(h1[src]+e1) + coalesced epilogue ----
    const float4* b4  = reinterpret_cast<const float4*>(bias_e);
    const float4* h14 = reinterpret_cast<const float4*>(g_h1);
    const float4* hu4 = reinterpret_cast<const float4*>(g_hu2);
    const float4* hv4 = reinterpret_cast<const float4*>(g_hv2);
    #pragma unroll
    for (int it = 0; it < 4; it++) {
        int i = tid + it * 256;
        int e = i >> 4, q = i & 15;
        if (e < nE) {
            int s = sSrc[e], d2 = sDst[e];
            // scatter: g_agg[dst] += h1[src] + e1
            float4 e1v = *reinterpret_cast<const float4*>(&sOut1[e * SO_PITCH + 4 * q]);
            float4 h1v = __ldg(h14 + (size_t)s * 16 + q);
            float* a = g_agg + (size_t)d2 * D + q * 4;
            asm volatile("red.global.add.v4.f32 [%0], {%1,%2,%3,%4};"
                         :: "l"(a),
                            "f"(h1v.x + e1v.x), "f"(h1v.y + e1v.y),
                            "f"(h1v.z + e1v.z), "f"(h1v.w + e1v.w)
                         : "memory");
            // epilogue: e_out = acc + hu2[src] + hv2[dst] + bias
            float4 av = *reinterpret_cast<const float4*>(&sOut0[e * SO_PITCH + 4 * q]);
            float4 hu = __ldg(hu4 + (size_t)s  * 16 + q);
            float4 hv = __ldg(hv4 + (size_t)d2 * 16 + q);
            float4 bb = __ldg(b4 + q);
            reinterpret_cast<float4*>(e_out)[(size_t)(ebase + e) * 16 + q] =
                make_float4(av.x + hu.x + hv.x + bb.x, av.y + hu.y + hv.y + bb.y,
                            av.z + hu.z + hv.z + bb.z, av.w + hu.w + hv.w + bb.w);
        }
    }
}

// ---------------------------------------------------------------------------
// K2 (R14 smem-weight version): single-phase —
//     h_out = S@Wv0 + X@Wv1 + (g_agg/max(deg,1))@Wv2 + bias_n
// ---------------------------------------------------------------------------
__global__ __launch_bounds__(256) void k_node_out(const float* __restrict__ S,
                                                  const float* __restrict__ X,
                                                  const float* __restrict__ Wv,
                                                  const float* __restrict__ bias_n,
                                                  float* __restrict__ h_out,
                                                  int N) {
    extern __shared__ float sm[];
    float (*sST)[65] = (float(*)[65])sm;                // 0..4160
    float (*sXT)[65] = (float(*)[65])(sm + 4160);       // ..8320
    float (*sHT)[65] = (float(*)[65])(sm + 8320);       // ..12480
    float* sWv = sm + 12480;                             // ..24768

    int tid = threadIdx.x;
    int base = blockIdx.x * 64;
    int nN = N - base; if (nN > 64) nN = 64;
    int tx = tid & 15, ty = tid >> 4;

    for (int i = tid; i < 3 * D * D; i += 256)
        sWv[i] = Wv[i];
    load_tile_T(sST, S, base, nN, tid);
    load_tile_T(sXT, X, base, nN, tid);
    // hn tile: load g_agg scaled by 1/max(deg,1), transposed
    #pragma unroll
    for (int it = 0; it < 4; it++) {
        int i = tid + it * 256;
        int n = i >> 4, q = i & 15;
        float4 v = make_float4(0.f, 0.f, 0.f, 0.f);
        if (n < nN) {
            v = reinterpret_cast<const float4*>(g_agg)[(size_t)(base + n) * 16 + q];
            float inv = 1.0f / fmaxf(g_deg[base + n], 1.0f);
            v.x *= inv; v.y *= inv; v.z *= inv; v.w *= inv;
        }
        sHT[4 * q + 0][n] = v.x;
        sHT[4 * q + 1][n] = v.y;
        sHT[4 * q + 2][n] = v.z;
        sHT[4 * q + 3][n] = v.w;
    }
    __syncthreads();

    float4 bb = reinterpret_cast<const float4*>(bias_n)[tx];
    float acc[4][4];
    #pragma unroll
    for (int r = 0; r < 4; r++) {
        acc[r][0] = bb.x; acc[r][1] = bb.y; acc[r][2] = bb.z; acc[r][3] = bb.w;
    }

    #pragma unroll 8
    for (int k = 0; k < D; k++) {
        float4 wS = *reinterpret_cast<const float4*>(&sWv[k * D + tx * 4]);
        float4 wX = *reinterpret_cast<const float4*>(&sWv[(D + k) * D + tx * 4]);
        float4 wH = *reinterpret_cast<const float4*>(&sWv[(2 * D + k) * D + tx * 4]);
        #pragma unroll
        for (int r = 0; r < 4; r++) {
            float s = sST[k][ty * 4 + r];
            float x = sXT[k][ty * 4 + r];
            float h = sHT[k][ty * 4 + r];
            acc[r][0] += s * wS.x + x * wX.x + h * wH.x;
            acc[r][1] += s * wS.y + x * wX.y + h * wH.y;
            acc[r][2] += s * wS.z + x * wX.z + h * wH.z;
            acc[r][3] += s * wS.w + x * wX.w + h * wH.w;
        }
    }

    #pragma unroll
    for (int r = 0; r < 4; r++) {
        int n = ty * 4 + r;
        if (n >= nN) continue;
        reinterpret_cast<float4*>(h_out)[(size_t)(base + n) * 16 + tx] =
            make_float4(acc[r][0], acc[r][1], acc[r][2], acc[r][3]);
    }
}

// ---------------------------------------------------------------------------
extern "C" void kernel_launch(void* const* d_in, const int* in_sizes, int n_in,
                              void* d_out, int out_size) {
    const float* S      = (const float*)d_in[0];
    const float* X      = (const float*)d_in[1];
    const float* Ein    = (const float*)d_in[2];
    const int*   src    = (const int*)d_in[3];
    const int*   dst    = (const int*)d_in[4];
    const float* Wn2n_u = (const float*)d_in[5];
    const float* Wn2n_v = (const float*)d_in[6];
    const float* We2n   = (const float*)d_in[7];
    const float* bias_n = (const float*)d_in[8];
    const float* Wn2e_u = (const float*)d_in[9];
    const float* Wn2e_v = (const float*)d_in[10];
    const float* We2e   = (const float*)d_in[11];
    const float* bias_e = (const float*)d_in[12];

    int N = in_sizes[1] / D;
    int E = in_sizes[3];
    float* h_out = (float*)d_out;
    float* e_out = h_out + (size_t)N * D;

    const int SM_PRE  = 24704 * 4;                                   // 98816 B
    const int SM_OUT  = 24768 * 4;                                   // 99072 B
    const int SM_EDGE = (64 * SE_PITCH + 2 * 64 * SO_PITCH) * 4
                        + 128 * 4;                                   // 54784 B

    cudaFuncSetAttribute(k_node_pre, cudaFuncAttributeMaxDynamicSharedMemorySize, SM_PRE);
    cudaFuncSetAttribute(k_node_out, cudaFuncAttributeMaxDynamicSharedMemorySize, SM_OUT);
    cudaFuncSetAttribute(k_edge,     cudaFuncAttributeMaxDynamicSharedMemorySize, SM_EDGE);

    int nBlk = (N + 63) / 64;
    k_wprep<<<(3 * D * D + 2 * 2048 + 255) / 256, 256>>>(Wn2e_u, Wn2e_v, We2e, We2n);
    k_node_pre<<<nBlk, 256, SM_PRE>>>(S, X, Wn2n_u, N);
    k_edge<<<(E + 63) / 64, 256, SM_EDGE>>>(Ein, src, dst, bias_e, e_out, E);
    k_node_out<<<nBlk, 256, SM_OUT>>>(S, X, Wn2n_v, bias_n, h_out, N);
}